// round 7
// baseline (speedup 1.0000x reference)
#include <cuda_runtime.h>
#include <cuda_fp16.h>
#include <cstdint>

#define EPSF 1e-8f
#define COLS 8192
#define BS 64
#define NB 128          // quant-blocks per row
#define NCELL 256       // LUT cells over x_norm in [-1,1)
#define NTHREADS 256
#define MAGIC15 12582912.0f   // 1.5*2^23: keeps result in [2^23,2^24) binade
#define MBIAS 0x400000        // mantissa of MAGIC15

typedef unsigned int u32;

// monotone float<->u32 order-preserving keys (min/max via integer redux)
__device__ __forceinline__ u32 fkey(float f) {
    u32 b = __float_as_uint(f);
    return b ^ ((u32)((int)b >> 31) | 0x80000000u);
}
__device__ __forceinline__ float unkey(u32 k) {
    u32 m = (~(u32)((int)k >> 31)) | 0x80000000u;
    return __uint_as_float(k ^ m);
}

// One CTA per row (8192 floats). Warp w owns quant-blocks [16w, 16w+16).
// Iteration i: lanes 0-15 cover block 16w+2i, lanes 16-31 cover 16w+2i+1
// (float4 per lane; each warp-iter touches 512 contiguous bytes, coalesced).
//
// R7 = R6 with the magic rounding made EXACT:
//  fcell = fmaf(x, s1, s2)        (one FMA, unrounded; also the compare value)
//  fbig  = fcell + MAGIC15        (separate FADD -> round-half-even(fcell))
//  ic    = mantissa(fbig) - 0x400000
// No pre-rounded addend, so ic == round(fcell) exactly.
__global__ __launch_bounds__(NTHREADS, 4)
void nf4_kernel(const float* __restrict__ x, float* __restrict__ out)
{
    __shared__ float2 lut[NCELL + 1];   // {midpoint_cell, bits(half2(t_lo,t_hi))}
    __shared__ float2 qc[NB];           // {a, b} per quant-block
    __shared__ float scale_s[NB];
    __shared__ float bmin_s[NB];
    __shared__ float t_s[16];
    __shared__ float m_s[15];           // midpoints, in cell coordinates
    __shared__ float sm_smin, sm_smax;

    const int tid  = threadIdx.x;
    const int lane = tid & 31;
    const int warp = tid >> 5;
    const long long row_base = (long long)blockIdx.x * COLS;
    const u32 hmask = (lane < 16) ? 0x0000FFFFu : 0xFFFF0000u;

    // ---- phase 0: NF4 table (ndtri at midpoints, normalized, fp16-rounded) ----
    if (tid < 16) {
        // ndtri(p) = sqrt(2)*erfinv(2p-1); sqrt(2) cancels in max-abs norm.
        float p   = (2.0f * ((float)tid + 0.5f)) / 16.0f - 1.0f;
        float q   = erfinvf(p);
        float q0  = erfinvf(2.0f * 0.5f  / 16.0f - 1.0f);
        float q15 = erfinvf(2.0f * 15.5f / 16.0f - 1.0f);
        float qmax = fmaxf(fabsf(q0), fabsf(q15));
        t_s[tid] = __half2float(__float2half(q / qmax));
    }
    __syncthreads();
    if (tid < 15) {
        // boundary between level tid and tid+1 in cell coords:
        // cell(x_norm) = (x_norm + 1) * 128
        m_s[tid] = ((t_s[tid] + t_s[tid + 1]) * 0.5f + 1.0f) * 128.0f;
    }
    __syncthreads();

    // ---- phase 0b: range LUT, cell c covers fcell in [c-0.5, c+0.5)
    // (round-to-nearest indexing). Min midpoint gap ~10.8 cells -> each cell
    // straddles at most one boundary. Strict '>' matches argmin's
    // first-index tie rule (tie -> lower level).
    for (int c = tid; c <= NCELL; c += NTHREADS) {
        int jlo = 0, jhi = 0;
        float fc = (float)c;
        #pragma unroll
        for (int k = 0; k < 15; k++) {
            jlo += (m_s[k] < fc - 0.5f) ? 1 : 0;
            jhi += (m_s[k] < fc + 0.5f) ? 1 : 0;
        }
        float2 e;
        __half2 tp;
        if (jhi > jlo) { e.x = m_s[jlo]; tp = __halves2half2(__float2half(t_s[jlo]), __float2half(t_s[jlo + 1])); }
        else           { e.x = -1e30f;   tp = __halves2half2(__float2half(t_s[jlo]), __float2half(t_s[jlo]));     }
        e.y = __uint_as_float(*reinterpret_cast<u32*>(&tp));
        lut[c] = e;
    }
    __syncthreads();   // LUT ready before phase-1 quantize

    // ---- phase 1: single pass: load, block min/max, quantize, stash fp16 ----
    const int qb_base = warp * 16;
    u32 stash[16];                      // 8 iters x 2 packed half2
    #pragma unroll
    for (int i = 0; i < 8; i++) {
        int e = (qb_base + 2 * i) * BS + lane * 4;
        float4 v = *reinterpret_cast<const float4*>(x + row_base + e);
        // monotone keys: one encode per element feeds both min and max
        u32 k0 = fkey(v.x), k1 = fkey(v.y), k2 = fkey(v.z), k3 = fkey(v.w);
        u32 kmn = min(min(k0, k1), min(k2, k3));
        u32 kmx = max(max(k0, k1), max(k2, k3));
        kmn = __reduce_min_sync(hmask, kmn);   // 16-lane segment reduce
        kmx = __reduce_max_sync(hmask, kmx);
        float mn = unkey(kmn);
        float mx = unkey(kmx);
        float scale = mx - mn;          // exact fp32 subtract, as reference
        if ((lane & 15) == 0) {
            int qb = qb_base + 2 * i + (lane >> 4);
            bmin_s[qb]  = mn;
            scale_s[qb] = scale;
        }
        // cell(x) = 256*(x - mn)/(scale + eps) = x*s1 + s2
        float s1 = __fdividef(256.0f, scale + EPSF);   // MUFU.RCP + FMUL
        float s2 = -mn * s1;
        const float* vi = reinterpret_cast<const float*>(&v);
        u32 w01 = 0, w23 = 0;
        #pragma unroll
        for (int j = 0; j < 4; j++) {
            float fcell = fmaf(vi[j], s1, s2);   // unrounded (compare value)
            float fbig  = fcell + MAGIC15;       // FADD: RNE(fcell) in mantissa
            int ic = (int)(__float_as_uint(fbig) & 0x7FFFFFu) - MBIAS;
            ic = max(0, min(NCELL, ic));         // safety clamp
            float2 L = lut[ic];
            u32 h2 = __float_as_uint(L.y);
            u32 t16 = (fcell > L.x) ? (h2 >> 16) : (h2 & 0xffffu);
            if (j == 0) w01  = t16;
            if (j == 1) w01 |= t16 << 16;
            if (j == 2) w23  = t16;
            if (j == 3) w23 |= t16 << 16;
        }
        stash[2 * i]     = w01;
        stash[2 * i + 1] = w23;
    }
    __syncthreads();

    // ---- phase 2: row-level min/max of the 128 block scales ----
    if (warp == 0) {
        u32 a0 = fkey(scale_s[lane]);
        u32 a1 = fkey(scale_s[lane + 32]);
        u32 a2 = fkey(scale_s[lane + 64]);
        u32 a3 = fkey(scale_s[lane + 96]);
        u32 kmn = min(min(a0, a1), min(a2, a3));
        u32 kmx = max(max(a0, a1), max(a2, a3));
        kmn = __reduce_min_sync(0xFFFFFFFFu, kmn);
        kmx = __reduce_max_sync(0xFFFFFFFFu, kmx);
        if (lane == 0) { sm_smin = unkey(kmn); sm_smax = unkey(kmx); }
    }
    __syncthreads();

    // ---- phase 3: per-block output constants ----
    if (tid < NB) {
        float smin  = sm_smin, smax = sm_smax;
        float scale = scale_s[tid];
        float bmin  = bmin_s[tid];
        float d     = smax - smin;
        // double quantization of scale (8-bit, round-half-even = rintf)
        float sq    = rintf((scale - smin) / (d + EPSF) * 255.0f);
        float srec  = smin + sq / 255.0f * d;
        // out = (t+1)/2 * srec + bmin == t*a + b
        float a = srec * 0.5f;
        float b = a + bmin;
        qc[tid] = make_float2(a, b);
    }
    __syncthreads();

    // ---- phase 4: dequant from register stash, coalesced store ----
    #pragma unroll
    for (int i = 0; i < 8; i++) {
        int qb = qb_base + 2 * i + (lane >> 4);
        int e  = (qb_base + 2 * i) * BS + lane * 4;
        float2 ab = qc[qb];
        u32 w01 = stash[2 * i];
        u32 w23 = stash[2 * i + 1];
        __half2 h01 = *reinterpret_cast<__half2*>(&w01);
        __half2 h23 = *reinterpret_cast<__half2*>(&w23);
        float4 o;
        o.x = fmaf(__low2float(h01),  ab.x, ab.y);
        o.y = fmaf(__high2float(h01), ab.x, ab.y);
        o.z = fmaf(__low2float(h23),  ab.x, ab.y);
        o.w = fmaf(__high2float(h23), ab.x, ab.y);
        *reinterpret_cast<float4*>(out + row_base + e) = o;
    }
}

extern "C" void kernel_launch(void* const* d_in, const int* in_sizes, int n_in,
                              void* d_out, int out_size)
{
    const float* x = (const float*)d_in[0];
    float* out = (float*)d_out;
    int rows = in_sizes[0] / COLS;   // 2048
    nf4_kernel<<<rows, NTHREADS>>>(x, out);
}